// round 8
// baseline (speedup 1.0000x reference)
#include <cuda_runtime.h>

// COO SpMM, rows sorted — single fused kernel (no atomics/smem-tiles/memset).
//   Each 128-thread block handles 4 consecutive rows. 5 threads binary-search
//   the block's row boundaries into smem (replaces the separate row_ptr pass).
//   Warp per row; half-warps take even/odd edge positions so one LDG.128
//   gathers 2 edges; lane owns 4 features; uniform-address meta loads
//   (L1 broadcast). Cross-half shfl reduce, one coalesced store per row.
// Inputs: seq [50000*64 f32], vals [E f32], rows [E i32], cols [E i32]
// Output: [1, 50000, 64] f32

#define D_FEAT 64
#define FULL 0xffffffffu
#define ROWS_PER_BLOCK 4

__global__ __launch_bounds__(128, 12)
void spmm_fused_kernel(const float* __restrict__ seq,
                       const float* __restrict__ vals,
                       const int* __restrict__ rows,
                       const int* __restrict__ cols,
                       float* __restrict__ out,
                       int n_edges, int n_nodes) {
    __shared__ int s_ptr[ROWS_PER_BLOCK + 1];

    const int row_base = blockIdx.x * ROWS_PER_BLOCK;

    // 5 threads find lower_bound(rows, row_base + t). Upper tree levels are
    // L1/L2-resident across blocks; ~21 probes, overlapped with other blocks.
    if (threadIdx.x <= ROWS_PER_BLOCK) {
        const int target = row_base + threadIdx.x;
        int lo = 0, hi = n_edges;
        while (lo < hi) {
            int mid = (lo + hi) >> 1;
            if (rows[mid] < target) lo = mid + 1; else hi = mid;
        }
        s_ptr[threadIdx.x] = lo;
    }
    __syncthreads();

    const int warp = threadIdx.x >> 5;
    const int lane = threadIdx.x & 31;
    const int half = lane >> 4;       // 0: even-position edges, 1: odd
    const int fl   = lane & 15;       // feature lane: 4 floats
    const int row  = row_base + warp;
    if (row >= n_nodes) return;

    const int beg = s_ptr[warp];
    const int end = s_ptr[warp + 1];

    const float4* __restrict__ seq4 = reinterpret_cast<const float4*>(seq);
    float4 acc = make_float4(0.f, 0.f, 0.f, 0.f);

    int i = beg + half;

    // 4 edges per half per iteration; meta loads uniform within a half
    // (L1 broadcast); 4 back-to-back LDG.128 gathers, each covering 2 edges.
    for (; i + 6 < end; i += 8) {
        const int c0 = cols[i]     * (D_FEAT / 4);
        const int c1 = cols[i + 2] * (D_FEAT / 4);
        const int c2 = cols[i + 4] * (D_FEAT / 4);
        const int c3 = cols[i + 6] * (D_FEAT / 4);
        const float v0 = vals[i];
        const float v1 = vals[i + 2];
        const float v2 = vals[i + 4];
        const float v3 = vals[i + 6];

        const float4 x0 = seq4[c0 + fl];
        const float4 x1 = seq4[c1 + fl];
        const float4 x2 = seq4[c2 + fl];
        const float4 x3 = seq4[c3 + fl];

        acc.x = fmaf(v0, x0.x, acc.x); acc.y = fmaf(v0, x0.y, acc.y);
        acc.z = fmaf(v0, x0.z, acc.z); acc.w = fmaf(v0, x0.w, acc.w);
        acc.x = fmaf(v1, x1.x, acc.x); acc.y = fmaf(v1, x1.y, acc.y);
        acc.z = fmaf(v1, x1.z, acc.z); acc.w = fmaf(v1, x1.w, acc.w);
        acc.x = fmaf(v2, x2.x, acc.x); acc.y = fmaf(v2, x2.y, acc.y);
        acc.z = fmaf(v2, x2.z, acc.z); acc.w = fmaf(v2, x2.w, acc.w);
        acc.x = fmaf(v3, x3.x, acc.x); acc.y = fmaf(v3, x3.y, acc.y);
        acc.z = fmaf(v3, x3.z, acc.z); acc.w = fmaf(v3, x3.w, acc.w);
    }

    for (; i < end; i += 2) {
        const int   c = cols[i] * (D_FEAT / 4);
        const float v = vals[i];
        const float4 x = seq4[c + fl];
        acc.x = fmaf(v, x.x, acc.x); acc.y = fmaf(v, x.y, acc.y);
        acc.z = fmaf(v, x.z, acc.z); acc.w = fmaf(v, x.w, acc.w);
    }

    // Combine even/odd partial sums (same 4 features).
    acc.x += __shfl_xor_sync(FULL, acc.x, 16);
    acc.y += __shfl_xor_sync(FULL, acc.y, 16);
    acc.z += __shfl_xor_sync(FULL, acc.z, 16);
    acc.w += __shfl_xor_sync(FULL, acc.w, 16);

    if (half == 0)   // 16 lanes x float4 = 256B coalesced; zeros if empty row
        reinterpret_cast<float4*>(out)[row * (D_FEAT / 4) + fl] = acc;
}

extern "C" void kernel_launch(void* const* d_in, const int* in_sizes, int n_in,
                              void* d_out, int out_size) {
    const float* seq  = (const float*)d_in[0];
    const float* vals = (const float*)d_in[1];
    const int*   rows = (const int*)d_in[2];
    const int*   cols = (const int*)d_in[3];
    float*       out  = (float*)d_out;
    const int n_edges = in_sizes[1];
    const int n_nodes = out_size / D_FEAT;   // 50000

    const int n_blocks = (n_nodes + ROWS_PER_BLOCK - 1) / ROWS_PER_BLOCK;  // 12500
    spmm_fused_kernel<<<n_blocks, 128>>>(seq, vals, rows, cols, out,
                                         n_edges, n_nodes);
}

// round 9
// speedup vs baseline: 1.4989x; 1.4989x over previous
#include <cuda_runtime.h>

// COO SpMM with sorted rows -> CSR two-phase (round-7 structure, proven at
// the LTS cap), with phase A accelerated by interpolation-bracketed binary
// search (serial probe depth 21 -> ~13, deterministic fallback).
// Inputs: seq [50000*64 f32], vals [E f32], rows [E i32], cols [E i32]
// Output: [1, 50000, 64] f32

#define D_FEAT 64
#define MAX_NODES 50001
#define FULL 0xffffffffu
#define BRACKET 4096   // ~7 sigma of Binomial(E, r/N) deviation; fallback-safe

__device__ int g_row_ptr[MAX_NODES + 1];

__global__ void build_row_ptr_kernel(const int* __restrict__ rows,
                                     int n_edges, int n_nodes) {
    const int r = blockIdx.x * blockDim.x + threadIdx.x;
    if (r > n_nodes) return;

    // Interpolated bracket around the expected boundary position.
    const long long guess = (long long)r * n_edges / n_nodes;
    int lo = (int)guess - BRACKET; if (lo < 0) lo = 0;
    int hi = (int)guess + BRACKET; if (hi > n_edges) hi = n_edges;

    // Two independent verify probes (issued back-to-back, latency overlapped).
    const int pl = (lo > 0)       ? rows[lo - 1] : -1;        // must be < r
    const int ph = (hi < n_edges) ? rows[hi]     : 0x7fffffff; // must be >= r
    if (!(pl < r && ph >= r)) { lo = 0; hi = n_edges; }        // rare fallback

    while (lo < hi) {
        int mid = (lo + hi) >> 1;
        if (rows[mid] < r) lo = mid + 1; else hi = mid;
    }
    g_row_ptr[r] = lo;
}

__global__ __launch_bounds__(128, 12)
void spmm_csr_uload_kernel(const float* __restrict__ seq,
                           const float* __restrict__ vals,
                           const int* __restrict__ cols,
                           float* __restrict__ out,
                           int n_nodes) {
    const int row  = (blockIdx.x * blockDim.x + threadIdx.x) >> 5;
    const int lane = threadIdx.x & 31;
    const int half = lane >> 4;       // 0: even-position edges, 1: odd
    const int fl   = lane & 15;       // feature lane: 4 floats
    if (row >= n_nodes) return;

    const int beg = g_row_ptr[row];
    const int end = g_row_ptr[row + 1];

    const float4* __restrict__ seq4 = reinterpret_cast<const float4*>(seq);
    float4 acc = make_float4(0.f, 0.f, 0.f, 0.f);

    int i = beg + half;

    // 4 edges per half per iteration; meta loads uniform within a half
    // (L1 broadcast); 4 back-to-back LDG.128 gathers, each covering 2 edges.
    for (; i + 6 < end; i += 8) {
        const int c0 = cols[i]     * (D_FEAT / 4);
        const int c1 = cols[i + 2] * (D_FEAT / 4);
        const int c2 = cols[i + 4] * (D_FEAT / 4);
        const int c3 = cols[i + 6] * (D_FEAT / 4);
        const float v0 = vals[i];
        const float v1 = vals[i + 2];
        const float v2 = vals[i + 4];
        const float v3 = vals[i + 6];

        const float4 x0 = seq4[c0 + fl];
        const float4 x1 = seq4[c1 + fl];
        const float4 x2 = seq4[c2 + fl];
        const float4 x3 = seq4[c3 + fl];

        acc.x = fmaf(v0, x0.x, acc.x); acc.y = fmaf(v0, x0.y, acc.y);
        acc.z = fmaf(v0, x0.z, acc.z); acc.w = fmaf(v0, x0.w, acc.w);
        acc.x = fmaf(v1, x1.x, acc.x); acc.y = fmaf(v1, x1.y, acc.y);
        acc.z = fmaf(v1, x1.z, acc.z); acc.w = fmaf(v1, x1.w, acc.w);
        acc.x = fmaf(v2, x2.x, acc.x); acc.y = fmaf(v2, x2.y, acc.y);
        acc.z = fmaf(v2, x2.z, acc.z); acc.w = fmaf(v2, x2.w, acc.w);
        acc.x = fmaf(v3, x3.x, acc.x); acc.y = fmaf(v3, x3.y, acc.y);
        acc.z = fmaf(v3, x3.z, acc.z); acc.w = fmaf(v3, x3.w, acc.w);
    }

    // Remainder (<= 3 edges per half; halves differ by <= 1 edge).
    for (; i < end; i += 2) {
        const int   c = cols[i] * (D_FEAT / 4);
        const float v = vals[i];
        const float4 x = seq4[c + fl];
        acc.x = fmaf(v, x.x, acc.x); acc.y = fmaf(v, x.y, acc.y);
        acc.z = fmaf(v, x.z, acc.z); acc.w = fmaf(v, x.w, acc.w);
    }

    // Combine even/odd partial sums (same 4 features).
    acc.x += __shfl_xor_sync(FULL, acc.x, 16);
    acc.y += __shfl_xor_sync(FULL, acc.y, 16);
    acc.z += __shfl_xor_sync(FULL, acc.z, 16);
    acc.w += __shfl_xor_sync(FULL, acc.w, 16);

    if (half == 0)   // 16 lanes x float4 = 256B coalesced; zeros if empty row
        reinterpret_cast<float4*>(out)[row * (D_FEAT / 4) + fl] = acc;
}

extern "C" void kernel_launch(void* const* d_in, const int* in_sizes, int n_in,
                              void* d_out, int out_size) {
    const float* seq  = (const float*)d_in[0];
    const float* vals = (const float*)d_in[1];
    const int*   rows = (const int*)d_in[2];
    const int*   cols = (const int*)d_in[3];
    float*       out  = (float*)d_out;
    const int n_edges = in_sizes[1];
    const int n_nodes = out_size / D_FEAT;   // 50000

    const int tA = 256;
    build_row_ptr_kernel<<<(n_nodes + 1 + tA) / tA, tA>>>(rows, n_edges, n_nodes);

    // Phase B: one warp per row, 4 warps per 128-thread block.
    spmm_csr_uload_kernel<<<(n_nodes + 3) / 4, 128>>>(seq, vals, cols, out, n_nodes);
}